// round 17
// baseline (speedup 1.0000x reference)
#include <cuda_runtime.h>
#include <cuda_bf16.h>
#include <cuda_fp16.h>
#include <math.h>
#include <float.h>
#include <stdint.h>

#define N_NODES 50000
#define N_EDGES 800000
#define SLOPE 0.2f

#if defined(__CUDA_ARCH__) && (__CUDA_ARCH__ >= 900)
#define GRID_DEP_SYNC() cudaGridDependencySynchronize()
#else
#define GRID_DEP_SYNC()
#endif

// ---------------- scratch (device globals; no allocation allowed) ----------
__device__ float          g_gl[N_NODES * 128];  // fp16 views: [N,128] L1-2 / [N,40] L3
__device__ float          g_gr[N_NODES * 128];
__device__ __nv_bfloat16  g_hsb[N_NODES * 128]; // bf16 hidden h
__device__ __nv_bfloat16  g_wsb[4 * 16384];     // bf16 Wl1,Wr1,Wl2,Wr2
__device__ __nv_bfloat16  g_w3sb[2 * 8192];     // bf16 Wl3,Wr3 padded [128,64]
__device__ int            g_deg[N_NODES];
__device__ int            g_off[N_NODES];
__device__ int            g_cur[N_NODES];
__device__ int            g_bsum[64];
__device__ int            g_eidx[N_EDGES];

// 4 halfs (uint2) -> float4
__device__ __forceinline__ float4 h4tof4(uint2 r) {
    __half2 h0 = *reinterpret_cast<__half2*>(&r.x);
    __half2 h1 = *reinterpret_cast<__half2*>(&r.y);
    float2 f0 = __half22float2(h0), f1 = __half22float2(h1);
    return make_float4(f0.x, f0.y, f1.x, f1.y);
}

// fused convert: blocks 0-63 cvt Wl1,Wr1,Wl2,Wr2 -> g_wsb;
// blocks 64-79 cvt Wl3,Wr3 (40 cols, zero-padded to 64) -> g_w3sb.
__global__ void k_split_w(const float* __restrict__ w0, const float* __restrict__ w1,
                          const float* __restrict__ w2, const float* __restrict__ w3,
                          __nv_bfloat16* __restrict__ outb,
                          const float* __restrict__ w3a, const float* __restrict__ w3b,
                          __nv_bfloat16* __restrict__ out3b) {
    if (blockIdx.x < 64) {
        int i = (blockIdx.x * 256 + threadIdx.x) * 4;
        int sel = i >> 14;
        int o4 = i & 16383;
        const float* w = (sel == 0) ? w0 : (sel == 1) ? w1 : (sel == 2) ? w2 : w3;
        float4 v = *(const float4*)(w + o4);
        __nv_bfloat16 ob[4];
        ob[0] = __float2bfloat16(v.x); ob[1] = __float2bfloat16(v.y);
        ob[2] = __float2bfloat16(v.z); ob[3] = __float2bfloat16(v.w);
        *(uint2*)(outb + i) = *(uint2*)ob;
    } else {
        int g = (blockIdx.x - 64) * 256 + threadIdx.x;   // 0..4095
        int sel = g >> 11;
        int gg = g & 2047;
        int e0 = gg * 4;
        int k = e0 >> 6, c = e0 & 63;
        const float* w = sel ? w3b : w3a;
        __nv_bfloat16 ob[4];
        #pragma unroll
        for (int j = 0; j < 4; j++) {
            float v = (c + j < 40) ? w[k * 40 + c + j] : 0.f;
            ob[j] = __float2bfloat16(v);
        }
        *(uint2*)(out3b + sel * 8192 + k * 64 + c) = *(uint2*)ob;
    }
}

// ================= CSR construction ==========================================
__global__ void k_hist(const int* __restrict__ dst, int* __restrict__ deg) {
    int e = blockIdx.x * blockDim.x + threadIdx.x;
    if (e < N_EDGES) atomicAdd(&deg[dst[e]], 1);
}

__global__ __launch_bounds__(1024) void k_scan_part(
    const int* __restrict__ deg, int* __restrict__ off, int* __restrict__ bsum)
{
    __shared__ int sh[1024];
    int t = threadIdx.x;
    int i = blockIdx.x * 1024 + t;
    int v = (i < N_NODES) ? deg[i] : 0;
    sh[t] = v;
    __syncthreads();
    #pragma unroll
    for (int o = 1; o < 1024; o <<= 1) {
        int u = (t >= o) ? sh[t - o] : 0;
        __syncthreads();
        sh[t] += u;
        __syncthreads();
    }
    if (i < N_NODES) off[i] = sh[t] - v;
    if (t == 1023) bsum[blockIdx.x] = sh[t];
}

__global__ void k_scan_add(int* __restrict__ off, int* __restrict__ cur,
                           const int* __restrict__ bsum)
{
    __shared__ int base_sh;
    int i = blockIdx.x * blockDim.x + threadIdx.x;
    int b = (blockIdx.x * blockDim.x) >> 10;
    if (threadIdx.x == 0) {
        int s = 0;
        for (int j = 0; j < b; j++) s += bsum[j];
        base_sh = s;
    }
    __syncthreads();
    if (i >= N_NODES) return;
    int o = off[i] + base_sh;
    off[i] = o;
    cur[i] = o;
}

__global__ void k_scatter(const int* __restrict__ src, const int* __restrict__ dst,
                          int* __restrict__ cur, int* __restrict__ eidx)
{
    int e = blockIdx.x * blockDim.x + threadIdx.x;
    if (e >= N_EDGES) return;
    int p = atomicAdd(&cur[dst[e]], 1);
    eidx[p] = src[e];
}

// ================= tensor-core helpers =======================================
__device__ __forceinline__ uint32_t smem_u32(const void* p) {
    return (uint32_t)__cvta_generic_to_shared(p);
}
__device__ __forceinline__ void ldsm_x4(uint32_t& r0, uint32_t& r1, uint32_t& r2, uint32_t& r3, uint32_t addr) {
    asm volatile("ldmatrix.sync.aligned.m8n8.x4.shared.b16 {%0,%1,%2,%3},[%4];"
                 : "=r"(r0), "=r"(r1), "=r"(r2), "=r"(r3) : "r"(addr));
}
__device__ __forceinline__ void ldsm_x2_t(uint32_t& r0, uint32_t& r1, uint32_t addr) {
    asm volatile("ldmatrix.sync.aligned.m8n8.x2.trans.shared.b16 {%0,%1},[%2];"
                 : "=r"(r0), "=r"(r1) : "r"(addr));
}
__device__ __forceinline__ void mma_bf16c(float* d, const uint32_t* a, const uint32_t* b) {
    asm volatile("mma.sync.aligned.m16n8k16.row.col.f32.bf16.bf16.f32 "
                 "{%0,%1,%2,%3},{%4,%5,%6,%7},{%8,%9},{%0,%1,%2,%3};"
                 : "+f"(d[0]), "+f"(d[1]), "+f"(d[2]), "+f"(d[3])
                 : "r"(a[0]), "r"(a[1]), "r"(a[2]), "r"(a[3]), "r"(b[0]), "r"(b[1]));
}

// ================= TC dual GEMM (layers 1-2), pure bf16, fp16 output ========
template <bool RAW>
__global__ __launch_bounds__(256, 2) void k_gemm_tc2(
    const __nv_bfloat16* __restrict__ Ab, const float* __restrict__ Araw,
    const __nv_bfloat16* __restrict__ W1b, const __nv_bfloat16* __restrict__ W2b,
    __half* __restrict__ C1, __half* __restrict__ C2, int M)
{
    __shared__ __nv_bfloat16 Ah[64][40];
    __shared__ __nv_bfloat16 Wh[32][264];

    const int tid = threadIdx.x, lane = tid & 31, wid = tid >> 5;
    const int wm = wid & 1;
    const int wn = wid >> 1;
    const int r0 = blockIdx.x * 64;

    float d[2][8][4];
    #pragma unroll
    for (int i = 0; i < 2; i++)
        #pragma unroll
        for (int j = 0; j < 8; j++)
            #pragma unroll
            for (int k = 0; k < 4; k++) d[i][j][k] = 0.f;

    for (int kt = 0; kt < 4; kt++) {
        if (RAW) {
            #pragma unroll
            for (int i = 0; i < 2; i++) {
                int idx = tid + i * 256;
                int row = idx >> 3, q = idx & 7;
                float4 v = make_float4(0.f, 0.f, 0.f, 0.f);
                if (r0 + row < M)
                    v = *(const float4*)(Araw + (size_t)(r0 + row) * 128 + kt * 32 + q * 4);
                __nv_bfloat16 h[4];
                h[0] = __float2bfloat16(v.x); h[1] = __float2bfloat16(v.y);
                h[2] = __float2bfloat16(v.z); h[3] = __float2bfloat16(v.w);
                *(uint2*)&Ah[row][q * 4] = *(uint2*)h;
            }
            if (kt == 0) GRID_DEP_SYNC();
            #pragma unroll
            for (int i = 0; i < 4; i++) {
                int idx = tid + i * 256;
                int k = idx >> 5, q = idx & 31;
                const __nv_bfloat16* wp = (q < 16)
                    ? W1b + (size_t)(kt * 32 + k) * 128 + q * 8
                    : W2b + (size_t)(kt * 32 + k) * 128 + (q - 16) * 8;
                *(uint4*)&Wh[k][q * 8] = *(const uint4*)wp;
            }
        } else {
            #pragma unroll
            for (int i = 0; i < 4; i++) {
                int idx = tid + i * 256;
                int k = idx >> 5, q = idx & 31;
                const __nv_bfloat16* wp = (q < 16)
                    ? W1b + (size_t)(kt * 32 + k) * 128 + q * 8
                    : W2b + (size_t)(kt * 32 + k) * 128 + (q - 16) * 8;
                *(uint4*)&Wh[k][q * 8] = *(const uint4*)wp;
            }
            if (kt == 0) GRID_DEP_SYNC();
            {
                int idx = tid;
                int row = idx >> 2, q = idx & 3;
                uint4 p = make_uint4(0u, 0u, 0u, 0u);
                if (r0 + row < M)
                    p = *(const uint4*)(Ab + (size_t)(r0 + row) * 128 + kt * 32 + q * 8);
                *(uint4*)&Ah[row][q * 8] = p;
            }
        }
        __syncthreads();

        #pragma unroll
        for (int k16 = 0; k16 < 2; k16++) {
            uint32_t af[2][4], bfr[8][2];
            #pragma unroll
            for (int mf = 0; mf < 2; mf++) {
                uint32_t addr = smem_u32(
                    &Ah[wm * 32 + mf * 16 + (lane & 15)][k16 * 16 + (lane >> 4) * 8]);
                ldsm_x4(af[mf][0], af[mf][1], af[mf][2], af[mf][3], addr);
            }
            #pragma unroll
            for (int nf = 0; nf < 8; nf++) {
                uint32_t addr = smem_u32(
                    &Wh[k16 * 16 + (lane & 15)][wn * 64 + nf * 8]);
                ldsm_x2_t(bfr[nf][0], bfr[nf][1], addr);
            }
            #pragma unroll
            for (int mf = 0; mf < 2; mf++)
                #pragma unroll
                for (int nf = 0; nf < 8; nf++)
                    mma_bf16c(d[mf][nf], af[mf], bfr[nf]);
        }
        __syncthreads();
    }

    const int g = lane >> 2, t = lane & 3;
    __half* Cp = (wn < 2) ? C1 : C2;
    int cbase = (wn < 2) ? wn * 64 : (wn - 2) * 64;
    #pragma unroll
    for (int mf = 0; mf < 2; mf++) {
        #pragma unroll
        for (int nf = 0; nf < 8; nf++) {
            int row0 = r0 + wm * 32 + mf * 16 + g;
            int col = cbase + nf * 8 + t * 2;
            if (row0 < M)
                *(__half2*)(Cp + (size_t)row0 * 128 + col) =
                    __floats2half2_rn(d[mf][nf][0], d[mf][nf][1]);
            if (row0 + 8 < M)
                *(__half2*)(Cp + (size_t)(row0 + 8) * 128 + col) =
                    __floats2half2_rn(d[mf][nf][2], d[mf][nf][3]);
        }
    }
}

// ================= TC dual GEMM layer 3 (N=40 padded to 64, fp16 out) =======
__global__ __launch_bounds__(256, 2) void k_gemm_tc3(
    const __nv_bfloat16* __restrict__ Ab, const __nv_bfloat16* __restrict__ W3b,
    __half* __restrict__ C1, __half* __restrict__ C2, int M)
{
    __shared__ __nv_bfloat16 Ah[64][40];
    __shared__ __nv_bfloat16 Wh[32][136];

    const int tid = threadIdx.x, lane = tid & 31, wid = tid >> 5;
    const int wm = wid & 1;
    const int wn = wid >> 1;
    const int r0 = blockIdx.x * 64;

    float d[2][4][4];
    #pragma unroll
    for (int i = 0; i < 2; i++)
        #pragma unroll
        for (int j = 0; j < 4; j++)
            #pragma unroll
            for (int k = 0; k < 4; k++) d[i][j][k] = 0.f;

    for (int kt = 0; kt < 4; kt++) {
        #pragma unroll
        for (int i = 0; i < 2; i++) {
            int idx = tid + i * 256;
            int k = idx >> 4, q = idx & 15;
            const __nv_bfloat16* wp = W3b + ((q >= 8) ? 8192 : 0)
                                    + (size_t)(kt * 32 + k) * 64 + (q & 7) * 8;
            *(uint4*)&Wh[k][q * 8] = *(const uint4*)wp;
        }
        if (kt == 0) GRID_DEP_SYNC();
        {
            int idx = tid;
            int row = idx >> 2, q = idx & 3;
            uint4 p = make_uint4(0u, 0u, 0u, 0u);
            if (r0 + row < M)
                p = *(const uint4*)(Ab + (size_t)(r0 + row) * 128 + kt * 32 + q * 8);
            *(uint4*)&Ah[row][q * 8] = p;
        }
        __syncthreads();

        #pragma unroll
        for (int k16 = 0; k16 < 2; k16++) {
            uint32_t af[2][4], bfr[4][2];
            #pragma unroll
            for (int mf = 0; mf < 2; mf++) {
                uint32_t addr = smem_u32(
                    &Ah[wm * 32 + mf * 16 + (lane & 15)][k16 * 16 + (lane >> 4) * 8]);
                ldsm_x4(af[mf][0], af[mf][1], af[mf][2], af[mf][3], addr);
            }
            #pragma unroll
            for (int nf = 0; nf < 4; nf++) {
                uint32_t addr = smem_u32(
                    &Wh[k16 * 16 + (lane & 15)][wn * 32 + nf * 8]);
                ldsm_x2_t(bfr[nf][0], bfr[nf][1], addr);
            }
            #pragma unroll
            for (int mf = 0; mf < 2; mf++)
                #pragma unroll
                for (int nf = 0; nf < 4; nf++)
                    mma_bf16c(d[mf][nf], af[mf], bfr[nf]);
        }
        __syncthreads();
    }

    const int g = lane >> 2, t = lane & 3;
    __half* Cp = (wn < 2) ? C1 : C2;
    int cbase = (wn & 1) * 32;
    #pragma unroll
    for (int mf = 0; mf < 2; mf++) {
        #pragma unroll
        for (int nf = 0; nf < 4; nf++) {
            int row0 = r0 + wm * 32 + mf * 16 + g;
            int col = cbase + nf * 8 + t * 2;
            if (col >= 40) continue;
            if (row0 < M)
                *(__half2*)(Cp + (size_t)row0 * 40 + col) =
                    __floats2half2_rn(d[mf][nf][0], d[mf][nf][1]);
            if (row0 + 8 < M)
                *(__half2*)(Cp + (size_t)(row0 + 8) * 40 + col) =
                    __floats2half2_rn(d[mf][nf][2], d[mf][nf][3]);
        }
    }
}

// ================= node aggregation (H=4, F=32), half2 math, 2 edges/warp ===
__global__ __launch_bounds__(256) void k_node_h4(
    const uint4* __restrict__ glh, const uint4* __restrict__ grh,
    const float* __restrict__ att,
    const int* __restrict__ off, const int* __restrict__ deg,
    const int* __restrict__ eidx, __nv_bfloat16* __restrict__ houtb, int mode)
{
    int n = blockIdx.x * 8 + (threadIdx.x >> 5);
    if (n >= N_NODES) return;
    int lane = threadIdx.x & 31;
    int sub = lane >> 4;
    int ll = lane & 15;

    float4 t0 = __ldg((const float4*)att + 2 * ll);
    float4 t1 = __ldg((const float4*)att + 2 * ll + 1);
    __half2 t2[4];
    t2[0] = __floats2half2_rn(t0.x, t0.y); t2[1] = __floats2half2_rn(t0.z, t0.w);
    t2[2] = __floats2half2_rn(t1.x, t1.y); t2[3] = __floats2half2_rn(t1.z, t1.w);
    const __half2 slope2 = __floats2half2_rn(SLOPE, SLOPE);

    GRID_DEP_SYNC();

    uint4 braw = grh[(size_t)n * 16 + ll];
    __half2 b2[4];
    b2[0] = *(__half2*)&braw.x; b2[1] = *(__half2*)&braw.y;
    b2[2] = *(__half2*)&braw.z; b2[3] = *(__half2*)&braw.w;

    float f[8];
    #pragma unroll
    for (int i = 0; i < 8; i++) f[i] = 0.f;
    float dw = 0.f;

    int start = off[n], cnt = deg[n];
    for (int base = 0; base < cnt; base += 32) {
        int rem = cnt - base;
        int m = rem < 32 ? rem : 32;
        int eld = (lane < m) ? __ldg(&eidx[start + base + lane]) : 0;
        int hm = (m + 1) >> 1;
        for (int j = 0; j < hm; j++) {
            int idx = 2 * j + sub;
            int s = __shfl_sync(0xffffffffu, eld, idx);
            uint4 araw = __ldg(&glh[(size_t)s * 16 + ll]);
            __half2 a2[4];
            a2[0] = *(__half2*)&araw.x; a2[1] = *(__half2*)&araw.y;
            a2[2] = *(__half2*)&araw.z; a2[3] = *(__half2*)&araw.w;

            __half2 acc = __floats2half2_rn(0.f, 0.f);
            #pragma unroll
            for (int i = 0; i < 4; i++) {
                __half2 s2 = __hadd2(a2[i], b2[i]);
                __half2 e2 = __hmax2(s2, __hmul2(s2, slope2));
                acc = __hfma2(e2, t2[i], acc);
            }
            float2 pf = __half22float2(acc);
            float p = pf.x + pf.y;
            p += __shfl_xor_sync(0xffffffffu, p, 2);
            p += __shfl_xor_sync(0xffffffffu, p, 1);
            float w = (idx < m) ? __expf(p) : 0.f;

            #pragma unroll
            for (int i = 0; i < 4; i++) {
                float2 af = __half22float2(a2[i]);
                f[2 * i]     += w * af.x;
                f[2 * i + 1] += w * af.y;
            }
            dw += w;
        }
    }

    #pragma unroll
    for (int i = 0; i < 8; i++) f[i] += __shfl_xor_sync(0xffffffffu, f[i], 16);
    dw += __shfl_xor_sync(0xffffffffu, dw, 16);

    if (sub == 0) {
        float inv = 1.0f / (dw + 1e-16f);
        __nv_bfloat16 ob[8];
        #pragma unroll
        for (int i = 0; i < 8; i++) {
            float v = f[i] * inv;
            if (mode == 1) v = v > 0.f ? v : expm1f(v);
            else           v = fmaxf(v, 0.f);
            ob[i] = __float2bfloat16(v);
        }
        *(uint4*)(houtb + (size_t)n * 128 + 8 * ll) = *(uint4*)ob;
    }
}

// ================= node layer 3 + log_softmax (H=1, F=40, fp16 feats) =======
__global__ __launch_bounds__(256) void k_node_h1_lsm(
    const __half* __restrict__ glh, const __half* __restrict__ grh,
    const float* __restrict__ att,
    const int* __restrict__ off, const int* __restrict__ deg,
    const int* __restrict__ eidx, float* __restrict__ out)
{
    int n = blockIdx.x * 8 + (threadIdx.x >> 5);
    if (n >= N_NODES) return;
    int lane = threadIdx.x & 31;
    int sub = lane >> 4;
    int ll = lane & 15;

    float4 t = make_float4(0.f, 0.f, 0.f, 0.f);
    if (ll < 10) t = __ldg(&((const float4*)att)[ll]);

    GRID_DEP_SYNC();

    float4 b = make_float4(0.f, 0.f, 0.f, 0.f);
    if (ll < 10) b = h4tof4(*(const uint2*)(grh + (size_t)n * 40 + 4 * ll));

    float ax = 0.f, ay = 0.f, az = 0.f, aw = 0.f, dw = 0.f;

    int start = off[n], cnt = deg[n];
    for (int base = 0; base < cnt; base += 32) {
        int rem = cnt - base;
        int m = rem < 32 ? rem : 32;
        int eld = (lane < m) ? __ldg(&eidx[start + base + lane]) : 0;
        int hm = (m + 1) >> 1;
        for (int j = 0; j < hm; j++) {
            int idx = 2 * j + sub;
            int s = __shfl_sync(0xffffffffu, eld, idx);
            float4 a = make_float4(0.f, 0.f, 0.f, 0.f);
            float p = 0.f;
            if (ll < 10) {
                a = h4tof4(__ldg((const uint2*)(glh + (size_t)s * 40 + 4 * ll)));
                float vx = a.x + b.x; vx = vx > 0.f ? vx : SLOPE * vx;
                float vy = a.y + b.y; vy = vy > 0.f ? vy : SLOPE * vy;
                float vz = a.z + b.z; vz = vz > 0.f ? vz : SLOPE * vz;
                float vw = a.w + b.w; vw = vw > 0.f ? vw : SLOPE * vw;
                p = vx * t.x + vy * t.y + vz * t.z + vw * t.w;
            }
            p += __shfl_xor_sync(0xffffffffu, p, 8, 16);
            p += __shfl_xor_sync(0xffffffffu, p, 4, 16);
            p += __shfl_xor_sync(0xffffffffu, p, 2, 16);
            p += __shfl_xor_sync(0xffffffffu, p, 1, 16);
            float w = (idx < m) ? __expf(p) : 0.f;
            ax += w * a.x; ay += w * a.y; az += w * a.z; aw += w * a.w;
            dw += w;
        }
    }

    ax += __shfl_xor_sync(0xffffffffu, ax, 16);
    ay += __shfl_xor_sync(0xffffffffu, ay, 16);
    az += __shfl_xor_sync(0xffffffffu, az, 16);
    aw += __shfl_xor_sync(0xffffffffu, aw, 16);
    dw += __shfl_xor_sync(0xffffffffu, dw, 16);

    float inv = 1.0f / (dw + 1e-16f);
    float4 v = make_float4(ax * inv, ay * inv, az * inv, aw * inv);

    float mx = (ll < 10) ? fmaxf(fmaxf(v.x, v.y), fmaxf(v.z, v.w)) : -FLT_MAX;
    #pragma unroll
    for (int o = 8; o > 0; o >>= 1) mx = fmaxf(mx, __shfl_xor_sync(0xffffffffu, mx, o, 16));
    float ss = (ll < 10)
        ? (expf(v.x - mx) + expf(v.y - mx) + expf(v.z - mx) + expf(v.w - mx)) : 0.f;
    #pragma unroll
    for (int o = 8; o > 0; o >>= 1) ss += __shfl_xor_sync(0xffffffffu, ss, o, 16);
    float lse = mx + logf(ss);
    if (sub == 0 && ll < 10) {
        float4 r = make_float4(v.x - lse, v.y - lse, v.z - lse, v.w - lse);
        *(float4*)(out + (size_t)n * 40 + 4 * ll) = r;
    }
}

// ---------------- host -------------------------------------------------------
extern "C" void kernel_launch(void* const* d_in, const int* in_sizes, int n_in,
                              void* d_out, int out_size)
{
    const float* x    = (const float*)d_in[0];
    const float* Wl1  = (const float*)d_in[1];
    const float* Wr1  = (const float*)d_in[2];
    const float* att1 = (const float*)d_in[3];
    const float* Wl2  = (const float*)d_in[4];
    const float* Wr2  = (const float*)d_in[5];
    const float* att2 = (const float*)d_in[6];
    const float* Wl3  = (const float*)d_in[7];
    const float* Wr3  = (const float*)d_in[8];
    const float* att3 = (const float*)d_in[9];
    const int*   ei   = (const int*)d_in[10];
    const int* src = ei;
    const int* dst = ei + N_EDGES;
    float* out = (float*)d_out;

    float *gl, *gr;
    __nv_bfloat16 *hsb, *wsb, *w3sb;
    int *deg, *off, *cur, *bsum, *eidx;
    cudaGetSymbolAddress((void**)&gl,   g_gl);
    cudaGetSymbolAddress((void**)&gr,   g_gr);
    cudaGetSymbolAddress((void**)&hsb,  g_hsb);
    cudaGetSymbolAddress((void**)&wsb,  g_wsb);
    cudaGetSymbolAddress((void**)&w3sb, g_w3sb);
    cudaGetSymbolAddress((void**)&deg,  g_deg);
    cudaGetSymbolAddress((void**)&off,  g_off);
    cudaGetSymbolAddress((void**)&cur,  g_cur);
    cudaGetSymbolAddress((void**)&bsum, g_bsum);
    cudaGetSymbolAddress((void**)&eidx, g_eidx);

    __half* glh = (__half*)gl;
    __half* grh = (__half*)gr;

    const int GB = (N_NODES + 63) / 64;
    const int NB = (N_NODES + 7) / 8;
    const int NSCAN = (N_NODES + 1023) / 1024;

    static cudaStream_t s2 = nullptr;
    static cudaEvent_t evFork = nullptr, evJoin = nullptr;
    if (!s2) {
        cudaStreamCreateWithFlags(&s2, cudaStreamNonBlocking);
        cudaEventCreateWithFlags(&evFork, cudaEventDisableTiming);
        cudaEventCreateWithFlags(&evJoin, cudaEventDisableTiming);
    }

    cudaLaunchAttribute pdlAttr;
    pdlAttr.id = cudaLaunchAttributeProgrammaticStreamSerialization;
    pdlAttr.val.programmaticStreamSerializationAllowed = 1;
    cudaLaunchConfig_t cfg = {};
    cfg.blockDim = {256, 1, 1};
    cfg.stream = 0;
    cfg.attrs = &pdlAttr;
    cfg.numAttrs = 1;

    // ---- fork: CSR build on s2, concurrent with weight cvt + layer-1 GEMM
    cudaEventRecord(evFork, 0);
    cudaStreamWaitEvent(s2, evFork, 0);
    cudaMemsetAsync(deg, 0, N_NODES * sizeof(int), s2);
    k_hist<<<(N_EDGES + 255) / 256, 256, 0, s2>>>(dst, deg);
    k_scan_part<<<NSCAN, 1024, 0, s2>>>(deg, off, bsum);
    k_scan_add<<<(N_NODES + 255) / 256, 256, 0, s2>>>(off, cur, bsum);
    k_scatter<<<(N_EDGES + 255) / 256, 256, 0, s2>>>(src, dst, cur, eidx);
    cudaEventRecord(evJoin, s2);

    // main stream: weight cvt, then layer-1 GEMM (PDL: A=x ready, W pending)
    k_split_w<<<80, 256>>>(Wl1, Wr1, Wl2, Wr2, wsb, Wl3, Wr3, w3sb);
    {
        cfg.gridDim = {(unsigned)GB, 1, 1};
        const __nv_bfloat16* ab = nullptr;
        cudaLaunchKernelEx(&cfg, k_gemm_tc2<true>, ab, x,
                           (const __nv_bfloat16*)(wsb + 0 * 16384),
                           (const __nv_bfloat16*)(wsb + 1 * 16384),
                           glh, grh, (int)N_NODES);
    }
    cudaStreamWaitEvent(0, evJoin, 0);

    // ---- Layer 1 aggregate (PDL) ----
    {
        cfg.gridDim = {(unsigned)NB, 1, 1};
        cudaLaunchKernelEx(&cfg, k_node_h4,
                           (const uint4*)glh, (const uint4*)grh, att1,
                           (const int*)off, (const int*)deg, (const int*)eidx,
                           hsb, 1);
    }
    // ---- Layer 2 ----
    {
        cfg.gridDim = {(unsigned)GB, 1, 1};
        const float* araw = nullptr;
        cudaLaunchKernelEx(&cfg, k_gemm_tc2<false>, (const __nv_bfloat16*)hsb, araw,
                           (const __nv_bfloat16*)(wsb + 2 * 16384),
                           (const __nv_bfloat16*)(wsb + 3 * 16384),
                           glh, grh, (int)N_NODES);
    }
    {
        cfg.gridDim = {(unsigned)NB, 1, 1};
        cudaLaunchKernelEx(&cfg, k_node_h4,
                           (const uint4*)glh, (const uint4*)grh, att2,
                           (const int*)off, (const int*)deg, (const int*)eidx,
                           hsb, 2);
    }
    // ---- Layer 3 (TC GEMM fp16 out; fused aggregate + log_softmax) ----
    {
        cfg.gridDim = {(unsigned)GB, 1, 1};
        cudaLaunchKernelEx(&cfg, k_gemm_tc3, (const __nv_bfloat16*)hsb,
                           (const __nv_bfloat16*)w3sb, glh, grh, (int)N_NODES);
    }
    {
        cfg.gridDim = {(unsigned)NB, 1, 1};
        cudaLaunchKernelEx(&cfg, k_node_h1_lsm,
                           (const __half*)glh, (const __half*)grh, att3,
                           (const int*)off, (const int*)deg, (const int*)eidx,
                           out);
    }
}